// round 8
// baseline (speedup 1.0000x reference)
#include <cuda_runtime.h>
#include <cuda_bf16.h>

// Problem shape (fixed by the dataset)
#define B_  64
#define S_  512
#define H_  768
#define L_  9
#define NT  (B_ * S_)          // 32768 destination rows
#define WPAD 10                // W row padded 9 -> 10 floats (8B-aligned float2 LDS)

// Scratch: dest -> source-token map (within batch row), -1 = no source (fill row)
__device__ int g_srcmap[NT];

// ---------------------------------------------------------------------------
// Kernel 1: per-batch inclusive scan of valid_mask -> dest->src map.
// ---------------------------------------------------------------------------
__global__ __launch_bounds__(S_) void scan_kernel(const int* __restrict__ mask) {
    __shared__ int sh[S_];
    const int b = blockIdx.x;
    const int s = threadIdx.x;
    const int m = mask[b * S_ + s];
    sh[s] = m;
    __syncthreads();
#pragma unroll
    for (int off = 1; off < S_; off <<= 1) {
        int v = (s >= off) ? sh[s - off] : 0;
        __syncthreads();
        sh[s] += v;
        __syncthreads();
    }
    const int cum = sh[s];
    const int count = sh[S_ - 1];
    const int dest = m ? (cum - 1) : (count + (s - cum));
    g_srcmap[b * S_ + dest] = m ? s : -1;
}

// ---------------------------------------------------------------------------
// Kernel 2: fused GEMV(768x9) + bias + softmax per destination row.
// 8 lanes per token (each lane covers 96 of 768 elems), 4 tokens per warp.
// A group of 8 lanes reads one full contiguous 128B line per chunk step:
// 100% L1 wavefront efficiency despite the row gather.
// 256 threads -> 32 tokens per block -> 1024 blocks.
// ---------------------------------------------------------------------------
__global__ __launch_bounds__(256) void gemv_kernel(const float* __restrict__ seq,
                                                   const float* __restrict__ W,
                                                   const float* __restrict__ bias,
                                                   float* __restrict__ out) {
    __shared__ float Wsh[H_ * WPAD];
    __shared__ float bsh[L_];

    const int tid = threadIdx.x;
    // cooperative W load with row padding
    for (int idx = tid; idx < H_ * L_; idx += 256) {
        const int i = idx / L_;
        const int l = idx - i * L_;
        Wsh[i * WPAD + l] = W[idx];
    }
    if (tid < L_) bsh[tid] = bias[tid];
    __syncthreads();

    const int warp = tid >> 5;
    const int lane = tid & 31;
    const int grp  = lane >> 3;   // token group within warp: 0..3
    const int sub  = lane & 7;    // lane within group: 0..7

    const int t = blockIdx.x * 32 + warp * 4 + grp;    // destination row id
    const int bidx = t >> 9;                            // t / S_
    const int src  = g_srcmap[t];

    float acc[L_];
#pragma unroll
    for (int l = 0; l < L_; l++) acc[l] = 0.0f;

    if (src >= 0) {
        const float4* __restrict__ rp =
            reinterpret_cast<const float4*>(seq + ((size_t)(bidx << 9) + src) * H_);
        // 24 chunks of 32 floats; group of 8 lanes covers one 128B line per chunk
#pragma unroll 6
        for (int k = 0; k < H_ / 32; k++) {
            const float4 v = rp[8 * k + sub];
            const int ibase = 32 * k + 4 * sub;
            const float xv[4] = {v.x, v.y, v.z, v.w};
#pragma unroll
            for (int j = 0; j < 4; j++) {
                const float x = xv[j];
                const float2* __restrict__ wp =
                    reinterpret_cast<const float2*>(&Wsh[(ibase + j) * WPAD]);
                const float2 w01 = wp[0], w23 = wp[1], w45 = wp[2], w67 = wp[3];
                const float  w8  = Wsh[(ibase + j) * WPAD + 8];
                acc[0] += x * w01.x; acc[1] += x * w01.y;
                acc[2] += x * w23.x; acc[3] += x * w23.y;
                acc[4] += x * w45.x; acc[5] += x * w45.y;
                acc[6] += x * w67.x; acc[7] += x * w67.y;
                acc[8] += x * w8;
            }
        }
    }

    // reduce across the 8-lane group (butterfly -> all 8 lanes hold full sums)
#pragma unroll
    for (int l = 0; l < L_; l++) {
        acc[l] += __shfl_xor_sync(0xFFFFFFFFu, acc[l], 1);
        acc[l] += __shfl_xor_sync(0xFFFFFFFFu, acc[l], 2);
        acc[l] += __shfl_xor_sync(0xFFFFFFFFu, acc[l], 4);
        acc[l] += bsh[l];
    }

    // softmax over 9 labels
    float mx = acc[0];
#pragma unroll
    for (int l = 1; l < L_; l++) mx = fmaxf(mx, acc[l]);
    float sum = 0.0f;
#pragma unroll
    for (int l = 0; l < L_; l++) {
        acc[l] = __expf(acc[l] - mx);
        sum += acc[l];
    }
    const float inv = 1.0f / sum;

    // split the 9 stores across the 8 group lanes (values identical per group):
    // lane sub stores label sub; lane 0 additionally stores label 8.
    float* __restrict__ orow = out + (size_t)t * L_;
    orow[sub] = acc[sub] * inv;
    if (sub == 0) orow[8] = acc[8] * inv;
}

extern "C" void kernel_launch(void* const* d_in, const int* in_sizes, int n_in,
                              void* d_out, int out_size) {
    const float* seq  = (const float*)d_in[0];  // [64,512,768] f32
    const int*   mask = (const int*)  d_in[1];  // [64,512]     i32
    const float* W    = (const float*)d_in[2];  // [768,9]      f32
    const float* bias = (const float*)d_in[3];  // [9]          f32
    float* out = (float*)d_out;                 // [64,512,9]   f32

    // Maximize shared carveout so smem stops capping occupancy (3 -> ~6
    // blocks/SM). Host-side config, not stream-ordered; takes effect on the
    // correctness call before graph capture. Ignore errors defensively.
    (void)cudaFuncSetAttribute(gemv_kernel,
                               cudaFuncAttributePreferredSharedMemoryCarveout,
                               cudaSharedmemCarveoutMaxShared);

    scan_kernel<<<B_, S_>>>(mask);
    gemv_kernel<<<NT / 32, 256>>>(seq, W, bias, out);
}

// round 13
// speedup vs baseline: 2.0626x; 2.0626x over previous
#include <cuda_runtime.h>
#include <cuda_bf16.h>

#define B_   64
#define S_   512
#define H_   768
#define L_   9
#define NT   (B_ * S_)         // 32768 destination rows
#define NTILE (NT / 4)         // 8192 warp-tiles of 4 tokens
#define GRID  512              // gemv blocks (128 thr = 4 warps); 4 tiles/warp

__device__ int g_srcmap[NT];

// ---------------------------------------------------------------------------
// Kernel 1: per-batch inclusive scan of valid_mask -> dest->src map.
// ---------------------------------------------------------------------------
__global__ __launch_bounds__(S_) void scan_kernel(const int* __restrict__ mask) {
    __shared__ int sh[S_];
    const int b = blockIdx.x;
    const int s = threadIdx.x;
    const int m = mask[b * S_ + s];
    sh[s] = m;
    __syncthreads();
#pragma unroll
    for (int off = 1; off < S_; off <<= 1) {
        int v = (s >= off) ? sh[s - off] : 0;
        __syncthreads();
        sh[s] += v;
        __syncthreads();
    }
    const int cum = sh[s];
    const int count = sh[S_ - 1];
    const int dest = m ? (cum - 1) : (count + (s - cum));
    g_srcmap[b * S_ + dest] = m ? s : -1;
}

// ---------------------------------------------------------------------------
// Kernel 2: token-blocked GEMV(768x9) + bias + softmax.
// One warp processes 4 tokens; 32 lanes span a 128-wide H-chunk (lane -> 4
// consecutive floats). W is staged COLUMN-MAJOR (WshC[label][i]) so each lane
// fetches, per chunk, 9 conflict-free float4 LDS (8-lane phase = 128B
// contiguous = all 32 banks) amortized over 4 tokens x 36 FMAs.
// Partials (4 tok x 9 lab) reduced with a reduce-scatter shfl fold: after it,
// 8-lane group g holds the full logits of token g.
// ---------------------------------------------------------------------------
__global__ __launch_bounds__(128, 4) void gemv_kernel(const float* __restrict__ seq,
                                                      const float* __restrict__ W,
                                                      const float* __restrict__ bias,
                                                      float* __restrict__ out) {
    __shared__ float WshC[L_ * H_];          // 27,648 B, column-major: [l][i]

    // stage W transposed: W[i*9+l] -> WshC[l*768+i]
    for (int idx = threadIdx.x; idx < H_ * L_; idx += 128) {
        const int i = idx / L_;
        const int l = idx - i * L_;
        WshC[l * H_ + i] = W[idx];
    }
    __syncthreads();

    const int wid  = threadIdx.x >> 5;
    const int lane = threadIdx.x & 31;
    const unsigned FULL = 0xFFFFFFFFu;

    for (int tile = blockIdx.x * 4 + wid; tile < NTILE; tile += GRID * 4) {
        const int t_base = tile * 4;                 // 4 tokens, same batch row
        const int bidx   = t_base >> 9;
        const float* rowbase = seq + (size_t)bidx * (S_ * H_);

        bool val[4];
        const float4* rp[4];
#pragma unroll
        for (int ti = 0; ti < 4; ti++) {
            const int src = g_srcmap[t_base + ti];
            val[ti] = (src >= 0);
            rp[ti] = reinterpret_cast<const float4*>(
                rowbase + (size_t)(val[ti] ? src : 0) * H_);
        }

        float acc[4][L_];
#pragma unroll
        for (int ti = 0; ti < 4; ti++)
#pragma unroll
            for (int l = 0; l < L_; l++) acc[ti][l] = 0.0f;

        if (val[0] | val[1] | val[2] | val[3]) {
#pragma unroll
            for (int k = 0; k < H_ / 128; k++) {     // 6 chunks
                float4 x[4];
#pragma unroll
                for (int ti = 0; ti < 4; ti++) {
                    x[ti] = val[ti] ? rp[ti][k * 32 + lane]
                                    : make_float4(0.f, 0.f, 0.f, 0.f);
                }
                const int ibase = k * 128 + 4 * lane;
#pragma unroll
                for (int l = 0; l < L_; l++) {
                    const float4 wv = *reinterpret_cast<const float4*>(
                        &WshC[l * H_ + ibase]);
#pragma unroll
                    for (int ti = 0; ti < 4; ti++) {
                        acc[ti][l] += x[ti].x * wv.x + x[ti].y * wv.y
                                    + x[ti].z * wv.z + x[ti].w * wv.w;
                    }
                }
            }
        }

        // ---- reduce-scatter: fold tokens across lane halves, then butterfly
        const bool hi16 = (lane & 16) != 0;
        float b2[2][L_];
#pragma unroll
        for (int tp = 0; tp < 2; tp++)
#pragma unroll
            for (int l = 0; l < L_; l++) {
                const float send = hi16 ? acc[tp][l] : acc[tp + 2][l];
                const float keep = hi16 ? acc[tp + 2][l] : acc[tp][l];
                b2[tp][l] = keep + __shfl_xor_sync(FULL, send, 16);
            }
        const bool hi8 = (lane & 8) != 0;
        float c[L_];
#pragma unroll
        for (int l = 0; l < L_; l++) {
            const float send = hi8 ? b2[0][l] : b2[1][l];
            const float keep = hi8 ? b2[1][l] : b2[0][l];
            c[l] = keep + __shfl_xor_sync(FULL, send, 8);
        }
#pragma unroll
        for (int l = 0; l < L_; l++) {
            c[l] += __shfl_xor_sync(FULL, c[l], 4);
            c[l] += __shfl_xor_sync(FULL, c[l], 2);
            c[l] += __shfl_xor_sync(FULL, c[l], 1);
            c[l] += bias[l];
        }
        // 8-lane group g = lane>>3 now holds token g's 9 logits

        float mx = c[0];
#pragma unroll
        for (int l = 1; l < L_; l++) mx = fmaxf(mx, c[l]);
        float sum = 0.0f;
#pragma unroll
        for (int l = 0; l < L_; l++) {
            c[l] = __expf(c[l] - mx);
            sum += c[l];
        }
        const float inv = 1.0f / sum;

        const int t = lane >> 3;
        const int q = lane & 7;
        float* __restrict__ orow = out + (size_t)(t_base + t) * L_;
        orow[q] = c[q] * inv;
        if (q == 0) orow[8] = c[8] * inv;
    }
}

extern "C" void kernel_launch(void* const* d_in, const int* in_sizes, int n_in,
                              void* d_out, int out_size) {
    const float* seq  = (const float*)d_in[0];  // [64,512,768] f32
    const int*   mask = (const int*)  d_in[1];  // [64,512]     i32
    const float* W    = (const float*)d_in[2];  // [768,9]      f32
    const float* bias = (const float*)d_in[3];  // [9]          f32
    float* out = (float*)d_out;                 // [64,512,9]   f32

    // Max shared carveout: 4 blocks x 27.6KB per SM. Host-side, capture-legal
    // (verified effective in R8: occupancy responded to this attribute).
    (void)cudaFuncSetAttribute(gemv_kernel,
                               cudaFuncAttributePreferredSharedMemoryCarveout,
                               cudaSharedmemCarveoutMaxShared);

    scan_kernel<<<B_, S_>>>(mask);
    gemv_kernel<<<GRID, 128>>>(seq, W, bias, out);
}